// round 5
// baseline (speedup 1.0000x reference)
#include <cuda_runtime.h>
#include <cuda_fp16.h>
#include <cstdint>

#define NNODES 100000
#define HDIM   128
#define RWS    10
#define KHOPS  4
#define CDIM   40
#define NSAMP  (KHOPS * RWS)   // 40
#define NPB    16              // nodes per agg block (16 lanes each, 256 thr)

// Scratch ping-pong buffers in fp16 (25.6 MB each) — __device__ globals.
__device__ __half g_bufA[(size_t)NNODES * HDIM];
__device__ __half g_bufB[(size_t)NNODES * HDIM];
__device__ float  g_sdeg[NNODES];    // sqrt(deg)
__device__ float  g_isdeg[NNODES];   // rsqrt(deg)

__device__ __forceinline__ void h8_to_f8(uint4 r, float* f) {
    float2 v;
    v = __half22float2(*(__half2*)&r.x); f[0] = v.x; f[1] = v.y;
    v = __half22float2(((__half2*)&r.x)[1]); f[2] = v.x; f[3] = v.y;
    v = __half22float2(*(__half2*)&r.z); f[4] = v.x; f[5] = v.y;
    v = __half22float2(((__half2*)&r.z)[1]); f[6] = v.x; f[7] = v.y;
}

__device__ __forceinline__ uint4 f8_to_h8(const float* f) {
    uint4 r;
    ((__half2*)&r.x)[0] = __floats2half2_rn(f[0], f[1]);
    ((__half2*)&r.x)[1] = __floats2half2_rn(f[2], f[3]);
    ((__half2*)&r.z)[0] = __floats2half2_rn(f[4], f[5]);
    ((__half2*)&r.z)[1] = __floats2half2_rn(f[6], f[7]);
    return r;
}

// ---------------------------------------------------------------------------
// Tensor-core primitives (warp-level mma path)
// ---------------------------------------------------------------------------
__device__ __forceinline__ uint32_t smem_u32(const void* p) {
    return (uint32_t)__cvta_generic_to_shared(p);
}
__device__ __forceinline__ void ldsm_x4(uint32_t* r, uint32_t a) {
    asm volatile("ldmatrix.sync.aligned.m8n8.x4.shared.b16 {%0,%1,%2,%3}, [%4];"
                 : "=r"(r[0]), "=r"(r[1]), "=r"(r[2]), "=r"(r[3]) : "r"(a));
}
__device__ __forceinline__ void ldsm_x4_t(uint32_t* r, uint32_t a) {
    asm volatile("ldmatrix.sync.aligned.m8n8.x4.trans.shared.b16 {%0,%1,%2,%3}, [%4];"
                 : "=r"(r[0]), "=r"(r[1]), "=r"(r[2]), "=r"(r[3]) : "r"(a));
}
__device__ __forceinline__ void mma16816(float* c, const uint32_t* a, const uint32_t* b) {
    asm volatile(
        "mma.sync.aligned.m16n8k16.row.col.f32.f16.f16.f32 "
        "{%0,%1,%2,%3}, {%4,%5,%6,%7}, {%8,%9}, {%0,%1,%2,%3};"
        : "+f"(c[0]), "+f"(c[1]), "+f"(c[2]), "+f"(c[3])
        : "r"(a[0]), "r"(a[1]), "r"(a[2]), "r"(a[3]), "r"(b[0]), "r"(b[1]));
}

// Packed fp32x2 FMA (Blackwell): d = a*b + c on register pairs.
__device__ __forceinline__ void ffma2(unsigned long long& d,
                                      unsigned long long a,
                                      unsigned long long b,
                                      unsigned long long c) {
    asm("fma.rn.f32x2 %0, %1, %2, %3;" : "=l"(d) : "l"(a), "l"(b), "l"(c));
}

// ---------------------------------------------------------------------------
// Degree precompute: sqrt(deg), rsqrt(deg)
// ---------------------------------------------------------------------------
__global__ void __launch_bounds__(256) deg_prep_kernel(
    const float* __restrict__ deg, float* __restrict__ sdeg,
    float* __restrict__ isdeg)
{
    int i = blockIdx.x * 256 + threadIdx.x;
    if (i < NNODES) {
        float d = deg[i];
        sdeg[i]  = sqrtf(d);
        isdeg[i] = rsqrtf(d);
    }
}

// ---------------------------------------------------------------------------
// HMMA GEMM: C[M x 128] = A[M x K] @ W[K x 128] + bias.
// A fp32 or fp16, W fp32 (converted to fp16 while staging), fp32 accumulate,
// fp16 C. BM=128, BN=128, BK=16, 8 warps (4x2), 32x64 per warp.
// ---------------------------------------------------------------------------
template <typename TA>
__global__ void __launch_bounds__(256) hgemm_kernel(
    const TA* __restrict__ A, const float* __restrict__ W,
    const float* __restrict__ bias, __half* __restrict__ C,
    int M, int K)
{
    constexpr int AP = 24;   // As row pitch in halves
    constexpr int BP = 136;  // Bs row pitch in halves
    __shared__ __half As[2][128 * AP];
    __shared__ __half Bs[2][16 * BP];

    const int t    = threadIdx.x;
    const int lane = t & 31;
    const int wid  = t >> 5;
    const int warpRow = wid >> 1;
    const int warpCol = wid & 1;
    const int blockRow = blockIdx.x * 128;

    const int a_row = t >> 1;
    const int a_kg  = (t & 1) * 8;
    const int grow  = blockRow + a_row;
    const bool a_valid = (grow < M);

    const int b_r = t >> 4;
    const int b_n = (t & 15) * 8;

    float acc[2][8][4];
    #pragma unroll
    for (int mt = 0; mt < 2; mt++)
        #pragma unroll
        for (int nt = 0; nt < 8; nt++)
            #pragma unroll
            for (int q = 0; q < 4; q++) acc[mt][nt][q] = 0.0f;

    auto loadA = [&](int buf, int k0) {
        __half h8[8];
        if (a_valid) {
            if constexpr (sizeof(TA) == 4) {
                const float* p = (const float*)A + (size_t)grow * K + k0 + a_kg;
                float4 v0 = *(const float4*)p;
                float4 v1 = *(const float4*)(p + 4);
                h8[0] = __float2half_rn(v0.x); h8[1] = __float2half_rn(v0.y);
                h8[2] = __float2half_rn(v0.z); h8[3] = __float2half_rn(v0.w);
                h8[4] = __float2half_rn(v1.x); h8[5] = __float2half_rn(v1.y);
                h8[6] = __float2half_rn(v1.z); h8[7] = __float2half_rn(v1.w);
            } else {
                const __half* p = (const __half*)A + (size_t)grow * K + k0 + a_kg;
                *(uint4*)h8 = *(const uint4*)p;
            }
        } else {
            #pragma unroll
            for (int q = 0; q < 8; q++) h8[q] = __float2half_rn(0.0f);
        }
        *(uint4*)&As[buf][a_row * AP + a_kg] = *(uint4*)h8;
    };

    auto loadB = [&](int buf, int k0) {
        const float* p = W + (size_t)(k0 + b_r) * 128 + b_n;
        float4 v0 = *(const float4*)p;
        float4 v1 = *(const float4*)(p + 4);
        __half h8[8];
        h8[0] = __float2half_rn(v0.x); h8[1] = __float2half_rn(v0.y);
        h8[2] = __float2half_rn(v0.z); h8[3] = __float2half_rn(v0.w);
        h8[4] = __float2half_rn(v1.x); h8[5] = __float2half_rn(v1.y);
        h8[6] = __float2half_rn(v1.z); h8[7] = __float2half_rn(v1.w);
        *(uint4*)&Bs[buf][b_r * BP + b_n] = *(uint4*)h8;
    };

    loadA(0, 0);
    loadB(0, 0);
    __syncthreads();

    const int a_lr = lane & 15;
    const int a_lk = (lane >> 4) * 8;
    const int b_lr = (lane & 7) + ((lane >> 3) & 1) * 8;
    const int b_lcg = (lane >> 4) * 8;

    int buf = 0;
    for (int k0 = 0; k0 < K; k0 += 16) {
        const bool has_next = (k0 + 16 < K);
        if (has_next) {
            loadA(buf ^ 1, k0 + 16);
            loadB(buf ^ 1, k0 + 16);
        }

        uint32_t a[2][4];
        #pragma unroll
        for (int mt = 0; mt < 2; mt++) {
            uint32_t addr = smem_u32(
                &As[buf][(warpRow * 32 + mt * 16 + a_lr) * AP + a_lk]);
            ldsm_x4(a[mt], addr);
        }

        uint32_t b[8][2];
        #pragma unroll
        for (int ntp = 0; ntp < 4; ntp++) {
            uint32_t r4[4];
            uint32_t addr = smem_u32(
                &Bs[buf][b_lr * BP + warpCol * 64 + ntp * 16 + b_lcg]);
            ldsm_x4_t(r4, addr);
            b[ntp * 2 + 0][0] = r4[0]; b[ntp * 2 + 0][1] = r4[1];
            b[ntp * 2 + 1][0] = r4[2]; b[ntp * 2 + 1][1] = r4[3];
        }

        #pragma unroll
        for (int mt = 0; mt < 2; mt++)
            #pragma unroll
            for (int nt = 0; nt < 8; nt++)
                mma16816(acc[mt][nt], a[mt], b[nt]);

        if (has_next) {
            __syncthreads();
            buf ^= 1;
        }
    }

    float2 bb[8];
    #pragma unroll
    for (int nt = 0; nt < 8; nt++) {
        const int col = warpCol * 64 + nt * 8 + (lane & 3) * 2;
        bb[nt] = *(const float2*)&bias[col];
    }

    #pragma unroll
    for (int mt = 0; mt < 2; mt++) {
        const int r0 = blockRow + warpRow * 32 + mt * 16 + (lane >> 2);
        const int r1 = r0 + 8;
        #pragma unroll
        for (int nt = 0; nt < 8; nt++) {
            const int col = warpCol * 64 + nt * 8 + (lane & 3) * 2;
            if (r0 < M) {
                __half2 v = __floats2half2_rn(acc[mt][nt][0] + bb[nt].x,
                                              acc[mt][nt][1] + bb[nt].y);
                *(__half2*)(C + (size_t)r0 * 128 + col) = v;
            }
            if (r1 < M) {
                __half2 v = __floats2half2_rn(acc[mt][nt][2] + bb[nt].x,
                                              acc[mt][nt][3] + bb[nt].y);
                *(__half2*)(C + (size_t)r1 * 128 + col) = v;
            }
        }
    }
}

// ---------------------------------------------------------------------------
// Random-walk aggregation + ReLU. fp16 HFMA2 accumulation, dual accumulator
// sets (even/odd samples) combined in fp32. 256 threads = 16 nodes x 16 lanes.
// Per sample: LDS.64 (idx+half2 weight) + LDG.128 + 4 HFMA2.
// ---------------------------------------------------------------------------
__global__ void __launch_bounds__(256) agg_kernel(
    const __half* __restrict__ hin, __half* __restrict__ hout,
    const int* __restrict__ ends_l,     // [KHOPS][NNODES*RWS]
    const float* __restrict__ sdeg,
    const float* __restrict__ isdeg,
    const float* __restrict__ att_l)    // [KHOPS+1]
{
    __shared__ int2 sp[NPB][NSAMP];     // {endpoint idx, half2(w,w) bits}

    const int n0 = blockIdx.x * NPB;
    const int t  = threadIdx.x;

    #pragma unroll
    for (int i = t; i < NPB * NSAMP; i += 256) {
        const int nl = i / NSAMP;
        const int s  = i - nl * NSAMP;
        const int k  = s / RWS;
        const int r  = s - k * RWS;
        const int n  = n0 + nl;
        const int e  = ends_l[k * (NNODES * RWS) + n * RWS + r];
        const float w = att_l[k + 1] * (1.0f / RWS) * sdeg[n] * isdeg[e];
        __half2 wh = __float2half2_rn(w);
        int2 p; p.x = e; p.y = *(int*)&wh;
        sp[nl][s] = p;
    }
    __syncthreads();

    const int nl   = t >> 4;
    const int lane = t & 15;
    const int n    = n0 + nl;
    const __half* lbase = hin + lane * 8;

    __half2 a0[4], a1[4];
    {
        const __half2 att0h = __float2half2_rn(att_l[0]);
        uint4 self = *(const uint4*)(hin + (size_t)n * HDIM + lane * 8);
        const __half2* sv = (const __half2*)&self;
        const __half2 z = __floats2half2_rn(0.f, 0.f);
        #pragma unroll
        for (int q = 0; q < 4; q++) { a0[q] = __hmul2(att0h, sv[q]); a1[q] = z; }
    }

    #pragma unroll
    for (int s = 0; s < NSAMP; s += 2) {
        const int2 p0 = sp[nl][s];
        const int2 p1 = sp[nl][s + 1];
        uint4 v0 = *(const uint4*)(lbase + ((size_t)p0.x << 7));
        uint4 v1 = *(const uint4*)(lbase + ((size_t)p1.x << 7));
        const __half2 w0 = *(const __half2*)&p0.y;
        const __half2 w1 = *(const __half2*)&p1.y;
        const __half2* e0 = (const __half2*)&v0;
        const __half2* e1 = (const __half2*)&v1;
        #pragma unroll
        for (int q = 0; q < 4; q++) {
            a0[q] = __hfma2(w0, e0[q], a0[q]);
            a1[q] = __hfma2(w1, e1[q], a1[q]);
        }
    }

    float f[8];
    #pragma unroll
    for (int q = 0; q < 4; q++) {
        float2 u = __half22float2(a0[q]);
        float2 v = __half22float2(a1[q]);
        f[q * 2 + 0] = fmaxf(u.x + v.x, 0.0f);
        f[q * 2 + 1] = fmaxf(u.y + v.y, 0.0f);
    }
    *(uint4*)(hout + (size_t)n * HDIM + lane * 8) = f8_to_h8(f);
}

// ---------------------------------------------------------------------------
// Final: logits = h @ W2 + b2, then log_softmax over 40 classes.
// Packed f32x2 FMA; W2 smem read as ulonglong2 (LDS.128 -> two f32x2 operands).
// ---------------------------------------------------------------------------
__global__ void __launch_bounds__(128) final_kernel(
    const __half* __restrict__ h, const float* __restrict__ W2,
    const float* __restrict__ b2, float* __restrict__ out, int M)
{
    __shared__ float Ws[HDIM * CDIM];
    __shared__ float bs[CDIM];

    const int t = threadIdx.x;
    for (int i = t; i < HDIM * CDIM; i += 128) Ws[i] = W2[i];
    if (t < CDIM) bs[t] = b2[t];
    __syncthreads();

    const int row = blockIdx.x * 128 + t;
    if (row >= M) return;

    unsigned long long acc2[CDIM / 2];
    #pragma unroll
    for (int j = 0; j < CDIM / 2; j++) {
        float lo = bs[2 * j], hi = bs[2 * j + 1];
        asm("mov.b64 %0, {%1, %2};" : "=l"(acc2[j])
            : "r"(__float_as_uint(lo)), "r"(__float_as_uint(hi)));
    }

    const uint4* hp = (const uint4*)(h + (size_t)row * HDIM);
    for (int kc = 0; kc < HDIM / 8; kc++) {
        float f[8];
        h8_to_f8(hp[kc], f);
        #pragma unroll
        for (int kk = 0; kk < 8; kk++) {
            unsigned long long a2;
            asm("mov.b64 %0, {%1, %1};" : "=l"(a2)
                : "r"(__float_as_uint(f[kk])));
            const ulonglong2* wr =
                (const ulonglong2*)&Ws[(kc * 8 + kk) * CDIM];
            #pragma unroll
            for (int j4 = 0; j4 < CDIM / 4; j4++) {
                ulonglong2 w = wr[j4];
                ffma2(acc2[j4 * 2 + 0], a2, w.x, acc2[j4 * 2 + 0]);
                ffma2(acc2[j4 * 2 + 1], a2, w.y, acc2[j4 * 2 + 1]);
            }
        }
    }

    float acc[CDIM];
    #pragma unroll
    for (int j = 0; j < CDIM / 2; j++) {
        uint32_t lo, hi;
        asm("mov.b64 {%0, %1}, %2;" : "=r"(lo), "=r"(hi) : "l"(acc2[j]));
        acc[2 * j]     = __uint_as_float(lo);
        acc[2 * j + 1] = __uint_as_float(hi);
    }

    float m = acc[0];
    #pragma unroll
    for (int c = 1; c < CDIM; c++) m = fmaxf(m, acc[c]);
    float s = 0.0f;
    #pragma unroll
    for (int c = 0; c < CDIM; c++) s += __expf(acc[c] - m);
    const float lse = m + __logf(s);

    float* op = out + (size_t)row * CDIM;
    #pragma unroll
    for (int c = 0; c < CDIM; c++) op[c] = acc[c] - lse;
}

// ---------------------------------------------------------------------------
// Launch sequence. Inputs: x, degree, ends, att, W0, b0, W1, b1, W2, b2
// ---------------------------------------------------------------------------
extern "C" void kernel_launch(void* const* d_in, const int* in_sizes, int n_in,
                              void* d_out, int out_size)
{
    const float* x   = (const float*)d_in[0];
    const float* deg = (const float*)d_in[1];
    const int*   ends= (const int*)  d_in[2];
    const float* att = (const float*)d_in[3];
    const float* W0  = (const float*)d_in[4];
    const float* b0  = (const float*)d_in[5];
    const float* W1  = (const float*)d_in[6];
    const float* b1  = (const float*)d_in[7];
    const float* W2  = (const float*)d_in[8];
    const float* b2  = (const float*)d_in[9];
    float* out = (float*)d_out;

    __half *bufA = nullptr, *bufB = nullptr;
    float *sdeg = nullptr, *isdeg = nullptr;
    cudaGetSymbolAddress((void**)&bufA, g_bufA);
    cudaGetSymbolAddress((void**)&bufB, g_bufB);
    cudaGetSymbolAddress((void**)&sdeg, g_sdeg);
    cudaGetSymbolAddress((void**)&isdeg, g_isdeg);

    const int gridM   = (NNODES + 127) / 128;     // 782
    const int gridAgg = NNODES / NPB;             // 6250

    deg_prep_kernel<<<(NNODES + 255) / 256, 256>>>(deg, sdeg, isdeg);
    // Layer 0: h = x @ W0 + b0  -> bufA (fp16, tensor cores)
    hgemm_kernel<float><<<gridM, 256>>>(x, W0, b0, bufA, NNODES, 256);
    // Agg layer 0: bufA -> bufB (relu'd)
    agg_kernel<<<gridAgg, 256>>>(bufA, bufB,
                                 ends + 0 * (size_t)KHOPS * NNODES * RWS,
                                 sdeg, isdeg, att + 0 * (KHOPS + 1));
    // Layer 1: h = bufB @ W1 + b1 -> bufA (fp16, tensor cores)
    hgemm_kernel<__half><<<gridM, 256>>>(bufB, W1, b1, bufA, NNODES, 128);
    // Agg layer 1: bufA -> bufB (relu'd)
    agg_kernel<<<gridAgg, 256>>>(bufA, bufB,
                                 ends + 1 * (size_t)KHOPS * NNODES * RWS,
                                 sdeg, isdeg, att + 1 * (KHOPS + 1));
    // Final: logits + log_softmax -> out
    final_kernel<<<gridM, 128>>>(bufB, W2, b2, out, NNODES);
}

// round 6
// speedup vs baseline: 1.1037x; 1.1037x over previous
#include <cuda_runtime.h>
#include <cuda_fp16.h>
#include <cstdint>

#define NNODES 100000
#define HDIM   128
#define RWS    10
#define KHOPS  4
#define CDIM   40
#define NSAMP  (KHOPS * RWS)   // 40
#define NPB    16              // nodes per agg block (16 lanes each, 256 thr)

// Scratch ping-pong buffers in fp16 (25.6 MB each) — __device__ globals.
__device__ __half g_bufA[(size_t)NNODES * HDIM];
__device__ __half g_bufB[(size_t)NNODES * HDIM];
__device__ float  g_sdeg[NNODES];    // sqrt(deg)
__device__ float  g_isdeg[NNODES];   // rsqrt(deg)

__device__ __forceinline__ uint4 f8_to_h8(const float* f) {
    uint4 r;
    ((__half2*)&r.x)[0] = __floats2half2_rn(f[0], f[1]);
    ((__half2*)&r.x)[1] = __floats2half2_rn(f[2], f[3]);
    ((__half2*)&r.z)[0] = __floats2half2_rn(f[4], f[5]);
    ((__half2*)&r.z)[1] = __floats2half2_rn(f[6], f[7]);
    return r;
}

// ---------------------------------------------------------------------------
// Tensor-core primitives
// ---------------------------------------------------------------------------
__device__ __forceinline__ uint32_t smem_u32(const void* p) {
    return (uint32_t)__cvta_generic_to_shared(p);
}
__device__ __forceinline__ void ldsm_x4(uint32_t* r, uint32_t a) {
    asm volatile("ldmatrix.sync.aligned.m8n8.x4.shared.b16 {%0,%1,%2,%3}, [%4];"
                 : "=r"(r[0]), "=r"(r[1]), "=r"(r[2]), "=r"(r[3]) : "r"(a));
}
__device__ __forceinline__ void ldsm_x4_t(uint32_t* r, uint32_t a) {
    asm volatile("ldmatrix.sync.aligned.m8n8.x4.trans.shared.b16 {%0,%1,%2,%3}, [%4];"
                 : "=r"(r[0]), "=r"(r[1]), "=r"(r[2]), "=r"(r[3]) : "r"(a));
}
__device__ __forceinline__ void mma16816(float* c, const uint32_t* a, const uint32_t* b) {
    asm volatile(
        "mma.sync.aligned.m16n8k16.row.col.f32.f16.f16.f32 "
        "{%0,%1,%2,%3}, {%4,%5,%6,%7}, {%8,%9}, {%0,%1,%2,%3};"
        : "+f"(c[0]), "+f"(c[1]), "+f"(c[2]), "+f"(c[3])
        : "r"(a[0]), "r"(a[1]), "r"(a[2]), "r"(a[3]), "r"(b[0]), "r"(b[1]));
}

// ---------------------------------------------------------------------------
// Degree precompute: sqrt(deg), rsqrt(deg)
// ---------------------------------------------------------------------------
__global__ void __launch_bounds__(256) deg_prep_kernel(
    const float* __restrict__ deg, float* __restrict__ sdeg,
    float* __restrict__ isdeg)
{
    int i = blockIdx.x * 256 + threadIdx.x;
    if (i < NNODES) {
        float d = deg[i];
        sdeg[i]  = sqrtf(d);
        isdeg[i] = rsqrtf(d);
    }
}

// ---------------------------------------------------------------------------
// HMMA GEMM: C[M x 128] = A[M x K] @ W[K x 128] + bias.
// A fp32 or fp16 (converted while staging), W fp32 (converted), fp32 accum,
// fp16 C. BM=64, BN=128, BK=16, 4 warps (2x2), 32x64 per warp.
// More CTAs/SM than the 128x128 version -> better latency hiding.
// ---------------------------------------------------------------------------
template <typename TA>
__global__ void __launch_bounds__(128) hgemm_kernel(
    const TA* __restrict__ A, const float* __restrict__ W,
    const float* __restrict__ bias, __half* __restrict__ C,
    int M, int K)
{
    constexpr int AP = 24;   // As row pitch in halves (48 B)
    constexpr int BP = 136;  // Bs row pitch in halves (272 B)
    __shared__ __half As[2][64 * AP];
    __shared__ __half Bs[2][16 * BP];

    const int t    = threadIdx.x;
    const int lane = t & 31;
    const int wid  = t >> 5;
    const int warpRow = wid >> 1;     // 0..1 -> 32-row slab
    const int warpCol = wid & 1;      // 0..1 -> 64-col slab
    const int blockRow = blockIdx.x * 64;

    // A staging: 64 rows x 16 k halves; 2 threads/row, 8 halves each.
    const int a_row = t >> 1;
    const int a_kg  = (t & 1) * 8;
    const int grow  = blockRow + a_row;
    const bool a_valid = (grow < M);

    // B staging: 16 k-rows x 128 cols; thread -> (k-row, 16 cols).
    const int b_r = t >> 3;          // 0..15
    const int b_n = (t & 7) * 16;    // 0..112

    float acc[2][8][4];
    #pragma unroll
    for (int mt = 0; mt < 2; mt++)
        #pragma unroll
        for (int nt = 0; nt < 8; nt++)
            #pragma unroll
            for (int q = 0; q < 4; q++) acc[mt][nt][q] = 0.0f;

    auto loadA = [&](int buf, int k0) {
        __half h8[8];
        if (a_valid) {
            if constexpr (sizeof(TA) == 4) {
                const float* p = (const float*)A + (size_t)grow * K + k0 + a_kg;
                float4 v0 = *(const float4*)p;
                float4 v1 = *(const float4*)(p + 4);
                h8[0] = __float2half_rn(v0.x); h8[1] = __float2half_rn(v0.y);
                h8[2] = __float2half_rn(v0.z); h8[3] = __float2half_rn(v0.w);
                h8[4] = __float2half_rn(v1.x); h8[5] = __float2half_rn(v1.y);
                h8[6] = __float2half_rn(v1.z); h8[7] = __float2half_rn(v1.w);
            } else {
                const __half* p = (const __half*)A + (size_t)grow * K + k0 + a_kg;
                *(uint4*)h8 = *(const uint4*)p;
            }
        } else {
            #pragma unroll
            for (int q = 0; q < 8; q++) h8[q] = __float2half_rn(0.0f);
        }
        *(uint4*)&As[buf][a_row * AP + a_kg] = *(uint4*)h8;
    };

    auto loadB = [&](int buf, int k0) {
        const float* p = W + (size_t)(k0 + b_r) * 128 + b_n;
        __half h16[16];
        #pragma unroll
        for (int g = 0; g < 4; g++) {
            float4 v = *(const float4*)(p + g * 4);
            h16[g * 4 + 0] = __float2half_rn(v.x);
            h16[g * 4 + 1] = __float2half_rn(v.y);
            h16[g * 4 + 2] = __float2half_rn(v.z);
            h16[g * 4 + 3] = __float2half_rn(v.w);
        }
        *(uint4*)&Bs[buf][b_r * BP + b_n]     = *(uint4*)&h16[0];
        *(uint4*)&Bs[buf][b_r * BP + b_n + 8] = *(uint4*)&h16[8];
    };

    loadA(0, 0);
    loadB(0, 0);
    __syncthreads();

    const int a_lr = lane & 15;
    const int a_lk = (lane >> 4) * 8;
    const int b_lr = (lane & 7) + ((lane >> 3) & 1) * 8;
    const int b_lcg = (lane >> 4) * 8;

    int buf = 0;
    for (int k0 = 0; k0 < K; k0 += 16) {
        const bool has_next = (k0 + 16 < K);
        if (has_next) {
            loadA(buf ^ 1, k0 + 16);
            loadB(buf ^ 1, k0 + 16);
        }

        uint32_t a[2][4];
        #pragma unroll
        for (int mt = 0; mt < 2; mt++) {
            uint32_t addr = smem_u32(
                &As[buf][(warpRow * 32 + mt * 16 + a_lr) * AP + a_lk]);
            ldsm_x4(a[mt], addr);
        }

        uint32_t b[8][2];
        #pragma unroll
        for (int ntp = 0; ntp < 4; ntp++) {
            uint32_t r4[4];
            uint32_t addr = smem_u32(
                &Bs[buf][b_lr * BP + warpCol * 64 + ntp * 16 + b_lcg]);
            ldsm_x4_t(r4, addr);
            b[ntp * 2 + 0][0] = r4[0]; b[ntp * 2 + 0][1] = r4[1];
            b[ntp * 2 + 1][0] = r4[2]; b[ntp * 2 + 1][1] = r4[3];
        }

        #pragma unroll
        for (int mt = 0; mt < 2; mt++)
            #pragma unroll
            for (int nt = 0; nt < 8; nt++)
                mma16816(acc[mt][nt], a[mt], b[nt]);

        if (has_next) {
            __syncthreads();
            buf ^= 1;
        }
    }

    float2 bb[8];
    #pragma unroll
    for (int nt = 0; nt < 8; nt++) {
        const int col = warpCol * 64 + nt * 8 + (lane & 3) * 2;
        bb[nt] = *(const float2*)&bias[col];
    }

    #pragma unroll
    for (int mt = 0; mt < 2; mt++) {
        const int r0 = blockRow + warpRow * 32 + mt * 16 + (lane >> 2);
        const int r1 = r0 + 8;
        #pragma unroll
        for (int nt = 0; nt < 8; nt++) {
            const int col = warpCol * 64 + nt * 8 + (lane & 3) * 2;
            if (r0 < M) {
                __half2 v = __floats2half2_rn(acc[mt][nt][0] + bb[nt].x,
                                              acc[mt][nt][1] + bb[nt].y);
                *(__half2*)(C + (size_t)r0 * 128 + col) = v;
            }
            if (r1 < M) {
                __half2 v = __floats2half2_rn(acc[mt][nt][2] + bb[nt].x,
                                              acc[mt][nt][3] + bb[nt].y);
                *(__half2*)(C + (size_t)r1 * 128 + col) = v;
            }
        }
    }
}

// ---------------------------------------------------------------------------
// Random-walk aggregation + ReLU. fp16 HFMA2 dual accumulators, fp32 combine.
// 256 threads = 16 nodes x 16 lanes.
// ---------------------------------------------------------------------------
__global__ void __launch_bounds__(256) agg_kernel(
    const __half* __restrict__ hin, __half* __restrict__ hout,
    const int* __restrict__ ends_l,
    const float* __restrict__ sdeg,
    const float* __restrict__ isdeg,
    const float* __restrict__ att_l)
{
    __shared__ int2 sp[NPB][NSAMP];     // {endpoint idx, half2(w,w) bits}

    const int n0 = blockIdx.x * NPB;
    const int t  = threadIdx.x;

    #pragma unroll
    for (int i = t; i < NPB * NSAMP; i += 256) {
        const int nl = i / NSAMP;
        const int s  = i - nl * NSAMP;
        const int k  = s / RWS;
        const int r  = s - k * RWS;
        const int n  = n0 + nl;
        const int e  = ends_l[k * (NNODES * RWS) + n * RWS + r];
        const float w = att_l[k + 1] * (1.0f / RWS) * sdeg[n] * isdeg[e];
        __half2 wh = __float2half2_rn(w);
        int2 p; p.x = e; p.y = *(int*)&wh;
        sp[nl][s] = p;
    }
    __syncthreads();

    const int nl   = t >> 4;
    const int lane = t & 15;
    const int n    = n0 + nl;
    const __half* lbase = hin + lane * 8;

    __half2 a0[4], a1[4];
    {
        const __half2 att0h = __float2half2_rn(att_l[0]);
        uint4 self = *(const uint4*)(hin + (size_t)n * HDIM + lane * 8);
        const __half2* sv = (const __half2*)&self;
        const __half2 z = __floats2half2_rn(0.f, 0.f);
        #pragma unroll
        for (int q = 0; q < 4; q++) { a0[q] = __hmul2(att0h, sv[q]); a1[q] = z; }
    }

    #pragma unroll
    for (int s = 0; s < NSAMP; s += 2) {
        const int2 p0 = sp[nl][s];
        const int2 p1 = sp[nl][s + 1];
        uint4 v0 = *(const uint4*)(lbase + ((size_t)p0.x << 7));
        uint4 v1 = *(const uint4*)(lbase + ((size_t)p1.x << 7));
        const __half2 w0 = *(const __half2*)&p0.y;
        const __half2 w1 = *(const __half2*)&p1.y;
        const __half2* e0 = (const __half2*)&v0;
        const __half2* e1 = (const __half2*)&v1;
        #pragma unroll
        for (int q = 0; q < 4; q++) {
            a0[q] = __hfma2(w0, e0[q], a0[q]);
            a1[q] = __hfma2(w1, e1[q], a1[q]);
        }
    }

    float f[8];
    #pragma unroll
    for (int q = 0; q < 4; q++) {
        float2 u = __half22float2(a0[q]);
        float2 v = __half22float2(a1[q]);
        f[q * 2 + 0] = fmaxf(u.x + v.x, 0.0f);
        f[q * 2 + 1] = fmaxf(u.y + v.y, 0.0f);
    }
    *(uint4*)(hout + (size_t)n * HDIM + lane * 8) = f8_to_h8(f);
}

// ---------------------------------------------------------------------------
// Final: logits = h @ W2 + b2 (HMMA, N padded 40->64), fused log_softmax.
// BM=64, 4 warps, warp tile 16x64. One-shot smem staging (no k pipeline).
// Padded cols get bias -1e30 -> exp()=0, never the max.
// ---------------------------------------------------------------------------
__global__ void __launch_bounds__(128) final_kernel(
    const __half* __restrict__ h, const float* __restrict__ W2,
    const float* __restrict__ b2, float* __restrict__ out, int M)
{
    constexpr int AP = 136;  // As pitch (rows of 128 halves)
    constexpr int BP = 72;   // Bs pitch (rows of 64 halves)
    __shared__ __half As[64 * AP];
    __shared__ __half Bs[128 * BP];

    const int t    = threadIdx.x;
    const int lane = t & 31;
    const int wid  = t >> 5;
    const int blockRow = blockIdx.x * 64;

    // Stage B: W2 [128 k x 40] -> padded fp16 [128 x 64]. 1 k-row per thread.
    {
        const int r = t;           // k index 0..127
        __half h8[8];
        #pragma unroll
        for (int c0 = 0; c0 < 64; c0 += 8) {
            #pragma unroll
            for (int q = 0; q < 8; q++) {
                const int c = c0 + q;
                h8[q] = (c < CDIM) ? __float2half_rn(W2[r * CDIM + c])
                                   : __float2half_rn(0.0f);
            }
            *(uint4*)&Bs[r * BP + c0] = *(uint4*)h8;
        }
    }

    // Stage A: h rows [blockRow..blockRow+63] x 128 halves. 2 threads/row.
    {
        const int a_row = t >> 1;
        const int kg    = (t & 1) * 64;
        const int grow  = blockRow + a_row;
        if (grow < M) {
            const uint4* src = (const uint4*)(h + (size_t)grow * HDIM + kg);
            #pragma unroll
            for (int q = 0; q < 8; q++)
                *(uint4*)&As[a_row * AP + kg + q * 8] = src[q];
        } else {
            const uint4 z = make_uint4(0, 0, 0, 0);
            #pragma unroll
            for (int q = 0; q < 8; q++)
                *(uint4*)&As[a_row * AP + kg + q * 8] = z;
        }
    }
    __syncthreads();

    const int a_lr = lane & 15;
    const int a_lk = (lane >> 4) * 8;
    const int b_lr = (lane & 7) + ((lane >> 3) & 1) * 8;
    const int b_lcg = (lane >> 4) * 8;

    float acc[8][4];
    #pragma unroll
    for (int nt = 0; nt < 8; nt++)
        #pragma unroll
        for (int q = 0; q < 4; q++) acc[nt][q] = 0.0f;

    #pragma unroll
    for (int k0 = 0; k0 < HDIM; k0 += 16) {
        uint32_t a[4];
        ldsm_x4(a, smem_u32(&As[(wid * 16 + a_lr) * AP + k0 + a_lk]));

        uint32_t b[8][2];
        #pragma unroll
        for (int ntp = 0; ntp < 4; ntp++) {
            uint32_t r4[4];
            ldsm_x4_t(r4, smem_u32(&Bs[(k0 + b_lr) * BP + ntp * 16 + b_lcg]));
            b[ntp * 2 + 0][0] = r4[0]; b[ntp * 2 + 0][1] = r4[1];
            b[ntp * 2 + 1][0] = r4[2]; b[ntp * 2 + 1][1] = r4[3];
        }

        #pragma unroll
        for (int nt = 0; nt < 8; nt++)
            mma16816(acc[nt], a, b[nt]);
    }

    // Add bias (pad = -1e30), then fused log_softmax per row via quad shuffle.
    float v0[8][2], v1[8][2];   // row r0 / r1 logits (2 cols per nt)
    #pragma unroll
    for (int nt = 0; nt < 8; nt++) {
        const int col = nt * 8 + (lane & 3) * 2;
        const float bx = (col     < CDIM) ? b2[col]     : -1e30f;
        const float by = (col + 1 < CDIM) ? b2[col + 1] : -1e30f;
        v0[nt][0] = acc[nt][0] + bx; v0[nt][1] = acc[nt][1] + by;
        v1[nt][0] = acc[nt][2] + bx; v1[nt][1] = acc[nt][3] + by;
    }

    float m0 = -1e30f, m1 = -1e30f;
    #pragma unroll
    for (int nt = 0; nt < 8; nt++) {
        m0 = fmaxf(m0, fmaxf(v0[nt][0], v0[nt][1]));
        m1 = fmaxf(m1, fmaxf(v1[nt][0], v1[nt][1]));
    }
    m0 = fmaxf(m0, __shfl_xor_sync(0xffffffffu, m0, 1));
    m0 = fmaxf(m0, __shfl_xor_sync(0xffffffffu, m0, 2));
    m1 = fmaxf(m1, __shfl_xor_sync(0xffffffffu, m1, 1));
    m1 = fmaxf(m1, __shfl_xor_sync(0xffffffffu, m1, 2));

    float s0 = 0.0f, s1 = 0.0f;
    #pragma unroll
    for (int nt = 0; nt < 8; nt++) {
        s0 += __expf(v0[nt][0] - m0) + __expf(v0[nt][1] - m0);
        s1 += __expf(v1[nt][0] - m1) + __expf(v1[nt][1] - m1);
    }
    s0 += __shfl_xor_sync(0xffffffffu, s0, 1);
    s0 += __shfl_xor_sync(0xffffffffu, s0, 2);
    s1 += __shfl_xor_sync(0xffffffffu, s1, 1);
    s1 += __shfl_xor_sync(0xffffffffu, s1, 2);

    const float lse0 = m0 + __logf(s0);
    const float lse1 = m1 + __logf(s1);

    const int r0 = blockRow + wid * 16 + (lane >> 2);
    const int r1 = r0 + 8;
    #pragma unroll
    for (int nt = 0; nt < 5; nt++) {        // cols 0..39 only
        const int col = nt * 8 + (lane & 3) * 2;
        if (r0 < M) {
            float2 w = make_float2(v0[nt][0] - lse0, v0[nt][1] - lse0);
            *(float2*)(out + (size_t)r0 * CDIM + col) = w;
        }
        if (r1 < M) {
            float2 w = make_float2(v1[nt][0] - lse1, v1[nt][1] - lse1);
            *(float2*)(out + (size_t)r1 * CDIM + col) = w;
        }
    }
}

// ---------------------------------------------------------------------------
// Launch sequence. Inputs: x, degree, ends, att, W0, b0, W1, b1, W2, b2
// ---------------------------------------------------------------------------
extern "C" void kernel_launch(void* const* d_in, const int* in_sizes, int n_in,
                              void* d_out, int out_size)
{
    const float* x   = (const float*)d_in[0];
    const float* deg = (const float*)d_in[1];
    const int*   ends= (const int*)  d_in[2];
    const float* att = (const float*)d_in[3];
    const float* W0  = (const float*)d_in[4];
    const float* b0  = (const float*)d_in[5];
    const float* W1  = (const float*)d_in[6];
    const float* b1  = (const float*)d_in[7];
    const float* W2  = (const float*)d_in[8];
    const float* b2  = (const float*)d_in[9];
    float* out = (float*)d_out;

    __half *bufA = nullptr, *bufB = nullptr;
    float *sdeg = nullptr, *isdeg = nullptr;
    cudaGetSymbolAddress((void**)&bufA, g_bufA);
    cudaGetSymbolAddress((void**)&bufB, g_bufB);
    cudaGetSymbolAddress((void**)&sdeg, g_sdeg);
    cudaGetSymbolAddress((void**)&isdeg, g_isdeg);

    const int gridM   = (NNODES + 63) / 64;       // 1563
    const int gridAgg = NNODES / NPB;             // 6250

    deg_prep_kernel<<<(NNODES + 255) / 256, 256>>>(deg, sdeg, isdeg);
    // Layer 0: h = x @ W0 + b0  -> bufA (fp16, tensor cores)
    hgemm_kernel<float><<<gridM, 128>>>(x, W0, b0, bufA, NNODES, 256);
    // Agg layer 0: bufA -> bufB (relu'd)
    agg_kernel<<<gridAgg, 256>>>(bufA, bufB,
                                 ends + 0 * (size_t)KHOPS * NNODES * RWS,
                                 sdeg, isdeg, att + 0 * (KHOPS + 1));
    // Layer 1: h = bufB @ W1 + b1 -> bufA (fp16, tensor cores)
    hgemm_kernel<__half><<<gridM, 128>>>(bufB, W1, b1, bufA, NNODES, 128);
    // Agg layer 1: bufA -> bufB (relu'd)
    agg_kernel<<<gridAgg, 256>>>(bufA, bufB,
                                 ends + 1 * (size_t)KHOPS * NNODES * RWS,
                                 sdeg, isdeg, att + 1 * (KHOPS + 1));
    // Final: logits + fused log_softmax -> out (tensor cores)
    final_kernel<<<gridM, 128>>>(bufB, W2, b2, out, NNODES);
}

// round 7
// speedup vs baseline: 1.2098x; 1.0962x over previous
#include <cuda_runtime.h>
#include <cuda_fp16.h>
#include <cstdint>

#define NNODES 100000
#define NPAD   100096          // 782 * 128, padded row count for scratch
#define HDIM   128
#define RWS    10
#define KHOPS  4
#define CDIM   40
#define NSAMP  (KHOPS * RWS)   // 40
#define NPB    16              // nodes per agg block (16 lanes each, 256 thr)

// Scratch ping-pong buffers in fp16 — __device__ globals (zero-init).
__device__ __half g_bufA[(size_t)NPAD * HDIM];
__device__ __half g_bufB[(size_t)NPAD * HDIM];
__device__ float  g_sdeg[NNODES];    // sqrt(deg)
__device__ float  g_isdeg[NNODES];   // rsqrt(deg)

__device__ __forceinline__ uint4 f8_to_h8(const float* f) {
    uint4 r;
    ((__half2*)&r.x)[0] = __floats2half2_rn(f[0], f[1]);
    ((__half2*)&r.x)[1] = __floats2half2_rn(f[2], f[3]);
    ((__half2*)&r.z)[0] = __floats2half2_rn(f[4], f[5]);
    ((__half2*)&r.z)[1] = __floats2half2_rn(f[6], f[7]);
    return r;
}

// ---------------------------------------------------------------------------
// Tensor-core + async-copy primitives
// ---------------------------------------------------------------------------
__device__ __forceinline__ uint32_t smem_u32(const void* p) {
    return (uint32_t)__cvta_generic_to_shared(p);
}
__device__ __forceinline__ void ldsm_x4(uint32_t* r, uint32_t a) {
    asm volatile("ldmatrix.sync.aligned.m8n8.x4.shared.b16 {%0,%1,%2,%3}, [%4];"
                 : "=r"(r[0]), "=r"(r[1]), "=r"(r[2]), "=r"(r[3]) : "r"(a));
}
__device__ __forceinline__ void ldsm_x4_t(uint32_t* r, uint32_t a) {
    asm volatile("ldmatrix.sync.aligned.m8n8.x4.trans.shared.b16 {%0,%1,%2,%3}, [%4];"
                 : "=r"(r[0]), "=r"(r[1]), "=r"(r[2]), "=r"(r[3]) : "r"(a));
}
__device__ __forceinline__ void mma16816(float* c, const uint32_t* a, const uint32_t* b) {
    asm volatile(
        "mma.sync.aligned.m16n8k16.row.col.f32.f16.f16.f32 "
        "{%0,%1,%2,%3}, {%4,%5,%6,%7}, {%8,%9}, {%0,%1,%2,%3};"
        : "+f"(c[0]), "+f"(c[1]), "+f"(c[2]), "+f"(c[3])
        : "r"(a[0]), "r"(a[1]), "r"(a[2]), "r"(a[3]), "r"(b[0]), "r"(b[1]));
}
__device__ __forceinline__ void cp16(uint32_t dst, const void* src) {
    asm volatile("cp.async.cg.shared.global [%0], [%1], 16;"
                 :: "r"(dst), "l"(src));
}
__device__ __forceinline__ void cp16z(uint32_t dst, const void* src, int sz) {
    asm volatile("cp.async.cg.shared.global [%0], [%1], 16, %2;"
                 :: "r"(dst), "l"(src), "r"(sz));
}
__device__ __forceinline__ void cp_commit() {
    asm volatile("cp.async.commit_group;");
}
__device__ __forceinline__ void cp_wait1() {
    asm volatile("cp.async.wait_group 1;");
}

// ---------------------------------------------------------------------------
// Degree precompute: sqrt(deg), rsqrt(deg)
// ---------------------------------------------------------------------------
__global__ void __launch_bounds__(256) deg_prep_kernel(
    const float* __restrict__ deg, float* __restrict__ sdeg,
    float* __restrict__ isdeg)
{
    int i = blockIdx.x * 256 + threadIdx.x;
    if (i < NNODES) {
        float d = deg[i];
        sdeg[i]  = sqrtf(d);
        isdeg[i] = rsqrtf(d);
    }
}

// ---------------------------------------------------------------------------
// Pipelined HMMA GEMM: C[NPAD x 128] = A[. x K] @ W[K x 128] + bias.
// BM=128, BN=128, BK=16, 256 threads, 8 warps (4x2), 32x64 per warp.
// W staged fully into smem fp16 at start. A streamed via cp.async 3-stage
// ring: fp16 A copied directly into ldmatrix layout; fp32 A staged raw and
// converted in-smem per stage. C is always a padded scratch buffer (no guard).
// ---------------------------------------------------------------------------
template <typename TA, int K>
__global__ void __launch_bounds__(256) hgemm_pipe(
    const TA* __restrict__ A, const float* __restrict__ W,
    const float* __restrict__ bias, __half* __restrict__ C, int M)
{
    constexpr bool F32A = (sizeof(TA) == 4);
    constexpr int  S  = 3;        // cp.async stages
    constexpr int  AP = 24;       // As row pitch (halves)
    constexpr int  BP = 136;      // Bs row pitch (halves)
    constexpr int  KT = K / 16;

    __shared__ __half Bs[K * BP];                       // full W, fp16
    __shared__ __half As[F32A ? 2 : S][128 * AP];       // ldmatrix A tiles
    __shared__ float  A32[F32A ? S * 128 * 16 : 1];     // raw fp32 staging

    const int t    = threadIdx.x;
    const int lane = t & 31;
    const int wid  = t >> 5;
    const int warpRow = wid >> 1;
    const int warpCol = wid & 1;
    const int blockRow = blockIdx.x * 128;

    const int a_row = t >> 1;
    const int a_kg  = (t & 1) * 8;
    const int grow  = blockRow + a_row;
    const bool a_valid = (grow < M);

    auto issueA = [&](int s, int k0) {
        if constexpr (F32A) {
            const float* src = A + (size_t)grow * K + k0 + a_kg;
            uint32_t d = smem_u32(&A32[s * 2048 + a_row * 16 + a_kg]);
            const int sz = a_valid ? 16 : 0;
            cp16z(d,      src,     sz);
            cp16z(d + 16, src + 4, sz);
        } else {
            const __half* src = (const __half*)A + (size_t)grow * K + k0 + a_kg;
            cp16(smem_u32(&As[s][a_row * AP + a_kg]), src);
        }
        cp_commit();
    };

    // Prologue: launch first S-1 A stages, then stage W while they fly.
    issueA(0, 0);
    issueA(1, 16);

    for (int idx = t * 8; idx < K * 128; idx += 2048) {
        const int row = idx >> 7;
        const int col = idx & 127;
        const float* p = W + row * 128 + col;
        float4 v0 = *(const float4*)p;
        float4 v1 = *(const float4*)(p + 4);
        __half h8[8];
        h8[0] = __float2half_rn(v0.x); h8[1] = __float2half_rn(v0.y);
        h8[2] = __float2half_rn(v0.z); h8[3] = __float2half_rn(v0.w);
        h8[4] = __float2half_rn(v1.x); h8[5] = __float2half_rn(v1.y);
        h8[6] = __float2half_rn(v1.z); h8[7] = __float2half_rn(v1.w);
        *(uint4*)&Bs[row * BP + col] = *(uint4*)h8;
    }
    __syncthreads();    // Bs visible to all

    float acc[2][8][4];
    #pragma unroll
    for (int mt = 0; mt < 2; mt++)
        #pragma unroll
        for (int nt = 0; nt < 8; nt++)
            #pragma unroll
            for (int q = 0; q < 4; q++) acc[mt][nt][q] = 0.0f;

    const int a_lr = lane & 15;
    const int a_lk = (lane >> 4) * 8;
    const int b_lr = (lane & 7) + ((lane >> 3) & 1) * 8;
    const int b_lcg = (lane >> 4) * 8;

    for (int kt = 0; kt < KT; kt++) {
        cp_wait1();          // stage kt's copies done (this thread)
        __syncthreads();     // ... for all threads

        int rb;
        if constexpr (F32A) {
            rb = kt & 1;
            const float* s32 = &A32[(kt % S) * 2048 + a_row * 16 + a_kg];
            float4 v0 = *(const float4*)s32;
            float4 v1 = *(const float4*)(s32 + 4);
            __half h8[8];
            h8[0] = __float2half_rn(v0.x); h8[1] = __float2half_rn(v0.y);
            h8[2] = __float2half_rn(v0.z); h8[3] = __float2half_rn(v0.w);
            h8[4] = __float2half_rn(v1.x); h8[5] = __float2half_rn(v1.y);
            h8[6] = __float2half_rn(v1.z); h8[7] = __float2half_rn(v1.w);
            *(uint4*)&As[rb][a_row * AP + a_kg] = *(uint4*)h8;
            __syncthreads();
        } else {
            rb = kt % S;
        }

        uint32_t a[2][4];
        #pragma unroll
        for (int mt = 0; mt < 2; mt++) {
            ldsm_x4(a[mt], smem_u32(
                &As[rb][(warpRow * 32 + mt * 16 + a_lr) * AP + a_lk]));
        }

        uint32_t b[8][2];
        #pragma unroll
        for (int ntp = 0; ntp < 4; ntp++) {
            uint32_t r4[4];
            ldsm_x4_t(r4, smem_u32(
                &Bs[(kt * 16 + b_lr) * BP + warpCol * 64 + ntp * 16 + b_lcg]));
            b[ntp * 2 + 0][0] = r4[0]; b[ntp * 2 + 0][1] = r4[1];
            b[ntp * 2 + 1][0] = r4[2]; b[ntp * 2 + 1][1] = r4[3];
        }

        #pragma unroll
        for (int mt = 0; mt < 2; mt++)
            #pragma unroll
            for (int nt = 0; nt < 8; nt++)
                mma16816(acc[mt][nt], a[mt], b[nt]);

        // Issue stage kt+S-1 (or an empty group to keep wait counts aligned).
        if (kt + S - 1 < KT) issueA((kt + S - 1) % S, (kt + S - 1) * 16);
        else                 cp_commit();
    }

    // Epilogue: add bias (fp32), store fp16. C is padded scratch: no guards.
    float2 bb[8];
    #pragma unroll
    for (int nt = 0; nt < 8; nt++) {
        const int col = warpCol * 64 + nt * 8 + (lane & 3) * 2;
        bb[nt] = *(const float2*)&bias[col];
    }

    #pragma unroll
    for (int mt = 0; mt < 2; mt++) {
        const int r0 = blockRow + warpRow * 32 + mt * 16 + (lane >> 2);
        const int r1 = r0 + 8;
        #pragma unroll
        for (int nt = 0; nt < 8; nt++) {
            const int col = warpCol * 64 + nt * 8 + (lane & 3) * 2;
            __half2 v0 = __floats2half2_rn(acc[mt][nt][0] + bb[nt].x,
                                           acc[mt][nt][1] + bb[nt].y);
            *(__half2*)(C + (size_t)r0 * 128 + col) = v0;
            __half2 v1 = __floats2half2_rn(acc[mt][nt][2] + bb[nt].x,
                                           acc[mt][nt][3] + bb[nt].y);
            *(__half2*)(C + (size_t)r1 * 128 + col) = v1;
        }
    }
}

// ---------------------------------------------------------------------------
// Random-walk aggregation + ReLU. fp16 HFMA2 dual accumulators, fp32 combine.
// 256 threads = 16 nodes x 16 lanes.
// ---------------------------------------------------------------------------
__global__ void __launch_bounds__(256) agg_kernel(
    const __half* __restrict__ hin, __half* __restrict__ hout,
    const int* __restrict__ ends_l,
    const float* __restrict__ sdeg,
    const float* __restrict__ isdeg,
    const float* __restrict__ att_l)
{
    __shared__ int2 sp[NPB][NSAMP];     // {endpoint idx, half2(w,w) bits}

    const int n0 = blockIdx.x * NPB;
    const int t  = threadIdx.x;

    #pragma unroll
    for (int i = t; i < NPB * NSAMP; i += 256) {
        const int nl = i / NSAMP;
        const int s  = i - nl * NSAMP;
        const int k  = s / RWS;
        const int r  = s - k * RWS;
        const int n  = n0 + nl;
        const int e  = ends_l[k * (NNODES * RWS) + n * RWS + r];
        const float w = att_l[k + 1] * (1.0f / RWS) * sdeg[n] * isdeg[e];
        __half2 wh = __float2half2_rn(w);
        int2 p; p.x = e; p.y = *(int*)&wh;
        sp[nl][s] = p;
    }
    __syncthreads();

    const int nl   = t >> 4;
    const int lane = t & 15;
    const int n    = n0 + nl;
    const __half* lbase = hin + lane * 8;

    __half2 a0[4], a1[4];
    {
        const __half2 att0h = __float2half2_rn(att_l[0]);
        uint4 self = *(const uint4*)(hin + (size_t)n * HDIM + lane * 8);
        const __half2* sv = (const __half2*)&self;
        const __half2 z = __floats2half2_rn(0.f, 0.f);
        #pragma unroll
        for (int q = 0; q < 4; q++) { a0[q] = __hmul2(att0h, sv[q]); a1[q] = z; }
    }

    #pragma unroll
    for (int s = 0; s < NSAMP; s += 2) {
        const int2 p0 = sp[nl][s];
        const int2 p1 = sp[nl][s + 1];
        uint4 v0 = *(const uint4*)(lbase + ((size_t)p0.x << 7));
        uint4 v1 = *(const uint4*)(lbase + ((size_t)p1.x << 7));
        const __half2 w0 = *(const __half2*)&p0.y;
        const __half2 w1 = *(const __half2*)&p1.y;
        const __half2* e0 = (const __half2*)&v0;
        const __half2* e1 = (const __half2*)&v1;
        #pragma unroll
        for (int q = 0; q < 4; q++) {
            a0[q] = __hfma2(w0, e0[q], a0[q]);
            a1[q] = __hfma2(w1, e1[q], a1[q]);
        }
    }

    float f[8];
    #pragma unroll
    for (int q = 0; q < 4; q++) {
        float2 u = __half22float2(a0[q]);
        float2 v = __half22float2(a1[q]);
        f[q * 2 + 0] = fmaxf(u.x + v.x, 0.0f);
        f[q * 2 + 1] = fmaxf(u.y + v.y, 0.0f);
    }
    *(uint4*)(hout + (size_t)n * HDIM + lane * 8) = f8_to_h8(f);
}

// ---------------------------------------------------------------------------
// Final: logits = h @ W2 + b2 (HMMA, N padded 40->64), fused log_softmax.
// BM=64, 4 warps, warp tile 16x64. Padded cols: bias -1e30 -> never max.
// ---------------------------------------------------------------------------
__global__ void __launch_bounds__(128) final_kernel(
    const __half* __restrict__ h, const float* __restrict__ W2,
    const float* __restrict__ b2, float* __restrict__ out, int M)
{
    constexpr int AP = 136;  // As pitch (rows of 128 halves)
    constexpr int BP = 72;   // Bs pitch (rows of 64 halves)
    __shared__ __half As[64 * AP];
    __shared__ __half Bs[128 * BP];

    const int t    = threadIdx.x;
    const int lane = t & 31;
    const int wid  = t >> 5;
    const int blockRow = blockIdx.x * 64;

    // Stage B: W2 [128 k x 40] -> padded fp16 [128 x 64].
    {
        const int r = t;
        __half h8[8];
        #pragma unroll
        for (int c0 = 0; c0 < 64; c0 += 8) {
            #pragma unroll
            for (int q = 0; q < 8; q++) {
                const int c = c0 + q;
                h8[q] = (c < CDIM) ? __float2half_rn(W2[r * CDIM + c])
                                   : __float2half_rn(0.0f);
            }
            *(uint4*)&Bs[r * BP + c0] = *(uint4*)h8;
        }
    }

    // Stage A: h rows [blockRow..+63] x 128 halves (padded buffer, no guard).
    {
        const int a_row = t >> 1;
        const int kg    = (t & 1) * 64;
        const uint4* src = (const uint4*)(h + (size_t)(blockRow + a_row) * HDIM + kg);
        #pragma unroll
        for (int q = 0; q < 8; q++)
            *(uint4*)&As[a_row * AP + kg + q * 8] = src[q];
    }
    __syncthreads();

    const int a_lr = lane & 15;
    const int a_lk = (lane >> 4) * 8;
    const int b_lr = (lane & 7) + ((lane >> 3) & 1) * 8;
    const int b_lcg = (lane >> 4) * 8;

    float acc[8][4];
    #pragma unroll
    for (int nt = 0; nt < 8; nt++)
        #pragma unroll
        for (int q = 0; q < 4; q++) acc[nt][q] = 0.0f;

    #pragma unroll
    for (int k0 = 0; k0 < HDIM; k0 += 16) {
        uint32_t a[4];
        ldsm_x4(a, smem_u32(&As[(wid * 16 + a_lr) * AP + k0 + a_lk]));

        uint32_t b[8][2];
        #pragma unroll
        for (int ntp = 0; ntp < 4; ntp++) {
            uint32_t r4[4];
            ldsm_x4_t(r4, smem_u32(&Bs[(k0 + b_lr) * BP + ntp * 16 + b_lcg]));
            b[ntp * 2 + 0][0] = r4[0]; b[ntp * 2 + 0][1] = r4[1];
            b[ntp * 2 + 1][0] = r4[2]; b[ntp * 2 + 1][1] = r4[3];
        }

        #pragma unroll
        for (int nt = 0; nt < 8; nt++)
            mma16816(acc[nt], a, b[nt]);
    }

    float v0[8][2], v1[8][2];
    #pragma unroll
    for (int nt = 0; nt < 8; nt++) {
        const int col = nt * 8 + (lane & 3) * 2;
        const float bx = (col     < CDIM) ? b2[col]     : -1e30f;
        const float by = (col + 1 < CDIM) ? b2[col + 1] : -1e30f;
        v0[nt][0] = acc[nt][0] + bx; v0[nt][1] = acc[nt][1] + by;
        v1[nt][0] = acc[nt][2] + bx; v1[nt][1] = acc[nt][3] + by;
    }

    float m0 = -1e30f, m1 = -1e30f;
    #pragma unroll
    for (int nt = 0; nt < 8; nt++) {
        m0 = fmaxf(m0, fmaxf(v0[nt][0], v0[nt][1]));
        m1 = fmaxf(m1, fmaxf(v1[nt][0], v1[nt][1]));
    }
    m0 = fmaxf(m0, __shfl_xor_sync(0xffffffffu, m0, 1));
    m0 = fmaxf(m0, __shfl_xor_sync(0xffffffffu, m0, 2));
    m1 = fmaxf(m1, __shfl_xor_sync(0xffffffffu, m1, 1));
    m1 = fmaxf(m1, __shfl_xor_sync(0xffffffffu, m1, 2));

    float s0 = 0.0f, s1 = 0.0f;
    #pragma unroll
    for (int nt = 0; nt < 8; nt++) {
        s0 += __expf(v0[nt][0] - m0) + __expf(v0[nt][1] - m0);
        s1 += __expf(v1[nt][0] - m1) + __expf(v1[nt][1] - m1);
    }
    s0 += __shfl_xor_sync(0xffffffffu, s0, 1);
    s0 += __shfl_xor_sync(0xffffffffu, s0, 2);
    s1 += __shfl_xor_sync(0xffffffffu, s1, 1);
    s1 += __shfl_xor_sync(0xffffffffu, s1, 2);

    const float lse0 = m0 + __logf(s0);
    const float lse1 = m1 + __logf(s1);

    const int r0 = blockRow + wid * 16 + (lane >> 2);
    const int r1 = r0 + 8;
    #pragma unroll
    for (int nt = 0; nt < 5; nt++) {        // cols 0..39 only
        const int col = nt * 8 + (lane & 3) * 2;
        if (r0 < M) {
            float2 w = make_float2(v0[nt][0] - lse0, v0[nt][1] - lse0);
            *(float2*)(out + (size_t)r0 * CDIM + col) = w;
        }
        if (r1 < M) {
            float2 w = make_float2(v1[nt][0] - lse1, v1[nt][1] - lse1);
            *(float2*)(out + (size_t)r1 * CDIM + col) = w;
        }
    }
}

// ---------------------------------------------------------------------------
// Launch sequence. Inputs: x, degree, ends, att, W0, b0, W1, b1, W2, b2
// ---------------------------------------------------------------------------
extern "C" void kernel_launch(void* const* d_in, const int* in_sizes, int n_in,
                              void* d_out, int out_size)
{
    const float* x   = (const float*)d_in[0];
    const float* deg = (const float*)d_in[1];
    const int*   ends= (const int*)  d_in[2];
    const float* att = (const float*)d_in[3];
    const float* W0  = (const float*)d_in[4];
    const float* b0  = (const float*)d_in[5];
    const float* W1  = (const float*)d_in[6];
    const float* b1  = (const float*)d_in[7];
    const float* W2  = (const float*)d_in[8];
    const float* b2  = (const float*)d_in[9];
    float* out = (float*)d_out;

    __half *bufA = nullptr, *bufB = nullptr;
    float *sdeg = nullptr, *isdeg = nullptr;
    cudaGetSymbolAddress((void**)&bufA, g_bufA);
    cudaGetSymbolAddress((void**)&bufB, g_bufB);
    cudaGetSymbolAddress((void**)&sdeg, g_sdeg);
    cudaGetSymbolAddress((void**)&isdeg, g_isdeg);

    const int gridM   = NPAD / 128;               // 782
    const int gridF   = (NNODES + 63) / 64;       // 1563
    const int gridAgg = NNODES / NPB;             // 6250

    deg_prep_kernel<<<(NNODES + 255) / 256, 256>>>(deg, sdeg, isdeg);
    // Layer 0: h = x @ W0 + b0  -> bufA (fp16, cp.async-pipelined HMMA)
    hgemm_pipe<float, 256><<<gridM, 256>>>(x, W0, b0, bufA, NNODES);
    // Agg layer 0: bufA -> bufB (relu'd)
    agg_kernel<<<gridAgg, 256>>>(bufA, bufB,
                                 ends + 0 * (size_t)KHOPS * NNODES * RWS,
                                 sdeg, isdeg, att + 0 * (KHOPS + 1));
    // Layer 1: h = bufB @ W1 + b1 -> bufA
    hgemm_pipe<__half, 128><<<gridM, 256>>>(bufB, W1, b1, bufA, NNODES);
    // Agg layer 1: bufA -> bufB (relu'd)
    agg_kernel<<<gridAgg, 256>>>(bufA, bufB,
                                 ends + 1 * (size_t)KHOPS * NNODES * RWS,
                                 sdeg, isdeg, att + 1 * (KHOPS + 1));
    // Final: logits + fused log_softmax -> out (tensor cores)
    final_kernel<<<gridF, 128>>>(bufB, W2, b2, out, NNODES);
}

// round 8
// speedup vs baseline: 1.2146x; 1.0040x over previous
#include <cuda_runtime.h>
#include <cuda_fp16.h>
#include <cstdint>

#define NNODES 100000
#define NPAD   100096          // 782 * 128, padded row count for scratch
#define HDIM   128
#define RWS    10
#define KHOPS  4
#define CDIM   40
#define NSAMP  (KHOPS * RWS)   // 40
#define NPB    16              // nodes per agg block (16 lanes each, 256 thr)

// Scratch ping-pong buffers in fp16 — __device__ globals (zero-init).
__device__ __half g_bufA[(size_t)NPAD * HDIM];
__device__ __half g_bufB[(size_t)NPAD * HDIM];
__device__ float  g_sdeg[NNODES];    // sqrt(deg)
__device__ float  g_isdeg[NNODES];   // rsqrt(deg)

__device__ __forceinline__ uint4 f8_to_h8(const float* f) {
    uint4 r;
    ((__half2*)&r.x)[0] = __floats2half2_rn(f[0], f[1]);
    ((__half2*)&r.x)[1] = __floats2half2_rn(f[2], f[3]);
    ((__half2*)&r.z)[0] = __floats2half2_rn(f[4], f[5]);
    ((__half2*)&r.z)[1] = __floats2half2_rn(f[6], f[7]);
    return r;
}

// ---------------------------------------------------------------------------
// Tensor-core + async-copy primitives
// ---------------------------------------------------------------------------
__device__ __forceinline__ uint32_t smem_u32(const void* p) {
    return (uint32_t)__cvta_generic_to_shared(p);
}
__device__ __forceinline__ void ldsm_x4(uint32_t* r, uint32_t a) {
    asm volatile("ldmatrix.sync.aligned.m8n8.x4.shared.b16 {%0,%1,%2,%3}, [%4];"
                 : "=r"(r[0]), "=r"(r[1]), "=r"(r[2]), "=r"(r[3]) : "r"(a));
}
__device__ __forceinline__ void ldsm_x4_t(uint32_t* r, uint32_t a) {
    asm volatile("ldmatrix.sync.aligned.m8n8.x4.trans.shared.b16 {%0,%1,%2,%3}, [%4];"
                 : "=r"(r[0]), "=r"(r[1]), "=r"(r[2]), "=r"(r[3]) : "r"(a));
}
__device__ __forceinline__ void mma16816(float* c, const uint32_t* a, const uint32_t* b) {
    asm volatile(
        "mma.sync.aligned.m16n8k16.row.col.f32.f16.f16.f32 "
        "{%0,%1,%2,%3}, {%4,%5,%6,%7}, {%8,%9}, {%0,%1,%2,%3};"
        : "+f"(c[0]), "+f"(c[1]), "+f"(c[2]), "+f"(c[3])
        : "r"(a[0]), "r"(a[1]), "r"(a[2]), "r"(a[3]), "r"(b[0]), "r"(b[1]));
}
__device__ __forceinline__ void cp16(uint32_t dst, const void* src) {
    asm volatile("cp.async.cg.shared.global [%0], [%1], 16;"
                 :: "r"(dst), "l"(src));
}
__device__ __forceinline__ void cp16z(uint32_t dst, const void* src, int sz) {
    asm volatile("cp.async.cg.shared.global [%0], [%1], 16, %2;"
                 :: "r"(dst), "l"(src), "r"(sz));
}
__device__ __forceinline__ void cp_commit() {
    asm volatile("cp.async.commit_group;");
}
template <int N>
__device__ __forceinline__ void cp_wait() {
    asm volatile("cp.async.wait_group %0;" :: "n"(N));
}

// ---------------------------------------------------------------------------
// Degree precompute: sqrt(deg), rsqrt(deg)
// ---------------------------------------------------------------------------
__global__ void __launch_bounds__(256) deg_prep_kernel(
    const float* __restrict__ deg, float* __restrict__ sdeg,
    float* __restrict__ isdeg)
{
    int i = blockIdx.x * 256 + threadIdx.x;
    if (i < NNODES) {
        float d = deg[i];
        sdeg[i]  = sqrtf(d);
        isdeg[i] = rsqrtf(d);
    }
}

// ---------------------------------------------------------------------------
// Pipelined HMMA GEMM: C[NPAD x 128] = A[. x K] @ W[K x 128] + bias.
// BM=128, BN=128, BK=16, 256 threads, 8 warps (4x2), 32x64 per warp.
// W staged fully into smem fp16 at start. A streamed via cp.async 4-stage
// ring, wait_group 2 (2-3 stages genuinely in flight), next-stage copy issued
// BEFORE the current stage's MMAs. fp32 A staged raw + converted in-smem.
// ---------------------------------------------------------------------------
template <typename TA, int K>
__global__ void __launch_bounds__(256) hgemm_pipe(
    const TA* __restrict__ A, const float* __restrict__ W,
    const float* __restrict__ bias, __half* __restrict__ C, int M)
{
    constexpr bool F32A = (sizeof(TA) == 4);
    constexpr int  S  = 4;        // cp.async stages
    constexpr int  AP = 24;       // As row pitch (halves)
    constexpr int  BP = 136;      // Bs row pitch (halves)
    constexpr int  KT = K / 16;

    __shared__ __half Bs[K * BP];                       // full W, fp16
    __shared__ __half As[F32A ? 2 : S][128 * AP];       // ldmatrix A tiles
    __shared__ float  A32[F32A ? S * 128 * 16 : 1];     // raw fp32 staging

    const int t    = threadIdx.x;
    const int lane = t & 31;
    const int wid  = t >> 5;
    const int warpRow = wid >> 1;
    const int warpCol = wid & 1;
    const int blockRow = blockIdx.x * 128;

    const int a_row = t >> 1;
    const int a_kg  = (t & 1) * 8;
    const int grow  = blockRow + a_row;
    const bool a_valid = (grow < M);

    auto issueA = [&](int s, int k0) {
        if constexpr (F32A) {
            const float* src = A + (size_t)grow * K + k0 + a_kg;
            uint32_t d = smem_u32(&A32[s * 2048 + a_row * 16 + a_kg]);
            const int sz = a_valid ? 16 : 0;
            cp16z(d,      src,     sz);
            cp16z(d + 16, src + 4, sz);
        } else {
            const __half* src = (const __half*)A + (size_t)grow * K + k0 + a_kg;
            cp16(smem_u32(&As[s][a_row * AP + a_kg]), src);
        }
        cp_commit();
    };

    // Prologue: launch first S-1 A stages, then stage W while they fly.
    issueA(0, 0);
    issueA(1, 16);
    issueA(2, 32);

    for (int idx = t * 8; idx < K * 128; idx += 2048) {
        const int row = idx >> 7;
        const int col = idx & 127;
        const float* p = W + row * 128 + col;
        float4 v0 = *(const float4*)p;
        float4 v1 = *(const float4*)(p + 4);
        __half h8[8];
        h8[0] = __float2half_rn(v0.x); h8[1] = __float2half_rn(v0.y);
        h8[2] = __float2half_rn(v0.z); h8[3] = __float2half_rn(v0.w);
        h8[4] = __float2half_rn(v1.x); h8[5] = __float2half_rn(v1.y);
        h8[6] = __float2half_rn(v1.z); h8[7] = __float2half_rn(v1.w);
        *(uint4*)&Bs[row * BP + col] = *(uint4*)h8;
    }
    __syncthreads();    // Bs visible to all

    float acc[2][8][4];
    #pragma unroll
    for (int mt = 0; mt < 2; mt++)
        #pragma unroll
        for (int nt = 0; nt < 8; nt++)
            #pragma unroll
            for (int q = 0; q < 4; q++) acc[mt][nt][q] = 0.0f;

    const int a_lr = lane & 15;
    const int a_lk = (lane >> 4) * 8;
    const int b_lr = (lane & 7) + ((lane >> 3) & 1) * 8;
    const int b_lcg = (lane >> 4) * 8;

    for (int kt = 0; kt < KT; kt++) {
        cp_wait<2>();        // stage kt's copies done (all but 2 newest groups)
        __syncthreads();     // ... visible to all threads

        // Issue stage kt+S-1 immediately (overlaps with this stage's compute).
        // Target buffer (kt+S-1)%S == (kt-1)%S was fully consumed last stage
        // (the __syncthreads above orders those reads before these writes).
        if (kt + S - 1 < KT) issueA((kt + S - 1) % S, (kt + S - 1) * 16);
        else                 cp_commit();   // keep group counts aligned

        int rb;
        if constexpr (F32A) {
            rb = kt & 1;
            const float* s32 = &A32[(kt % S) * 2048 + a_row * 16 + a_kg];
            float4 v0 = *(const float4*)s32;
            float4 v1 = *(const float4*)(s32 + 4);
            __half h8[8];
            h8[0] = __float2half_rn(v0.x); h8[1] = __float2half_rn(v0.y);
            h8[2] = __float2half_rn(v0.z); h8[3] = __float2half_rn(v0.w);
            h8[4] = __float2half_rn(v1.x); h8[5] = __float2half_rn(v1.y);
            h8[6] = __float2half_rn(v1.z); h8[7] = __float2half_rn(v1.w);
            *(uint4*)&As[rb][a_row * AP + a_kg] = *(uint4*)h8;
            __syncthreads();
        } else {
            rb = kt % S;
        }

        uint32_t a[2][4];
        #pragma unroll
        for (int mt = 0; mt < 2; mt++) {
            ldsm_x4(a[mt], smem_u32(
                &As[rb][(warpRow * 32 + mt * 16 + a_lr) * AP + a_lk]));
        }

        uint32_t b[8][2];
        #pragma unroll
        for (int ntp = 0; ntp < 4; ntp++) {
            uint32_t r4[4];
            ldsm_x4_t(r4, smem_u32(
                &Bs[(kt * 16 + b_lr) * BP + warpCol * 64 + ntp * 16 + b_lcg]));
            b[ntp * 2 + 0][0] = r4[0]; b[ntp * 2 + 0][1] = r4[1];
            b[ntp * 2 + 1][0] = r4[2]; b[ntp * 2 + 1][1] = r4[3];
        }

        #pragma unroll
        for (int mt = 0; mt < 2; mt++)
            #pragma unroll
            for (int nt = 0; nt < 8; nt++)
                mma16816(acc[mt][nt], a[mt], b[nt]);
    }

    // Epilogue: add bias (fp32), store fp16. C is padded scratch: no guards.
    float2 bb[8];
    #pragma unroll
    for (int nt = 0; nt < 8; nt++) {
        const int col = warpCol * 64 + nt * 8 + (lane & 3) * 2;
        bb[nt] = *(const float2*)&bias[col];
    }

    #pragma unroll
    for (int mt = 0; mt < 2; mt++) {
        const int r0 = blockRow + warpRow * 32 + mt * 16 + (lane >> 2);
        const int r1 = r0 + 8;
        #pragma unroll
        for (int nt = 0; nt < 8; nt++) {
            const int col = warpCol * 64 + nt * 8 + (lane & 3) * 2;
            __half2 v0 = __floats2half2_rn(acc[mt][nt][0] + bb[nt].x,
                                           acc[mt][nt][1] + bb[nt].y);
            *(__half2*)(C + (size_t)r0 * 128 + col) = v0;
            __half2 v1 = __floats2half2_rn(acc[mt][nt][2] + bb[nt].x,
                                           acc[mt][nt][3] + bb[nt].y);
            *(__half2*)(C + (size_t)r1 * 128 + col) = v1;
        }
    }
}

// ---------------------------------------------------------------------------
// Random-walk aggregation + ReLU. fp16 HFMA2 dual accumulators, fp32 combine.
// 256 threads = 16 nodes x 16 lanes. 4 gather loads batched per iteration
// to raise per-thread MLP.
// ---------------------------------------------------------------------------
__global__ void __launch_bounds__(256) agg_kernel(
    const __half* __restrict__ hin, __half* __restrict__ hout,
    const int* __restrict__ ends_l,
    const float* __restrict__ sdeg,
    const float* __restrict__ isdeg,
    const float* __restrict__ att_l)
{
    __shared__ int2 sp[NPB][NSAMP];     // {endpoint idx, half2(w,w) bits}

    const int n0 = blockIdx.x * NPB;
    const int t  = threadIdx.x;

    #pragma unroll
    for (int i = t; i < NPB * NSAMP; i += 256) {
        const int nl = i / NSAMP;
        const int s  = i - nl * NSAMP;
        const int k  = s / RWS;
        const int r  = s - k * RWS;
        const int n  = n0 + nl;
        const int e  = ends_l[k * (NNODES * RWS) + n * RWS + r];
        const float w = att_l[k + 1] * (1.0f / RWS) * sdeg[n] * isdeg[e];
        __half2 wh = __float2half2_rn(w);
        int2 p; p.x = e; p.y = *(int*)&wh;
        sp[nl][s] = p;
    }
    __syncthreads();

    const int nl   = t >> 4;
    const int lane = t & 15;
    const int n    = n0 + nl;
    const __half* lbase = hin + lane * 8;

    __half2 a0[4], a1[4];
    {
        const __half2 att0h = __float2half2_rn(att_l[0]);
        uint4 self = *(const uint4*)(hin + (size_t)n * HDIM + lane * 8);
        const __half2* sv = (const __half2*)&self;
        const __half2 z = __floats2half2_rn(0.f, 0.f);
        #pragma unroll
        for (int q = 0; q < 4; q++) { a0[q] = __hmul2(att0h, sv[q]); a1[q] = z; }
    }

    #pragma unroll
    for (int s = 0; s < NSAMP; s += 4) {
        const int2 p0 = sp[nl][s];
        const int2 p1 = sp[nl][s + 1];
        const int2 p2 = sp[nl][s + 2];
        const int2 p3 = sp[nl][s + 3];
        uint4 v0 = *(const uint4*)(lbase + ((size_t)p0.x << 7));
        uint4 v1 = *(const uint4*)(lbase + ((size_t)p1.x << 7));
        uint4 v2 = *(const uint4*)(lbase + ((size_t)p2.x << 7));
        uint4 v3 = *(const uint4*)(lbase + ((size_t)p3.x << 7));
        const __half2 w0 = *(const __half2*)&p0.y;
        const __half2 w1 = *(const __half2*)&p1.y;
        const __half2 w2 = *(const __half2*)&p2.y;
        const __half2 w3 = *(const __half2*)&p3.y;
        const __half2* e0 = (const __half2*)&v0;
        const __half2* e1 = (const __half2*)&v1;
        const __half2* e2 = (const __half2*)&v2;
        const __half2* e3 = (const __half2*)&v3;
        #pragma unroll
        for (int q = 0; q < 4; q++) {
            a0[q] = __hfma2(w0, e0[q], a0[q]);
            a1[q] = __hfma2(w1, e1[q], a1[q]);
        }
        #pragma unroll
        for (int q = 0; q < 4; q++) {
            a0[q] = __hfma2(w2, e2[q], a0[q]);
            a1[q] = __hfma2(w3, e3[q], a1[q]);
        }
    }

    float f[8];
    #pragma unroll
    for (int q = 0; q < 4; q++) {
        float2 u = __half22float2(a0[q]);
        float2 v = __half22float2(a1[q]);
        f[q * 2 + 0] = fmaxf(u.x + v.x, 0.0f);
        f[q * 2 + 1] = fmaxf(u.y + v.y, 0.0f);
    }
    *(uint4*)(hout + (size_t)n * HDIM + lane * 8) = f8_to_h8(f);
}

// ---------------------------------------------------------------------------
// Final: logits = h @ W2 + b2 (HMMA, N padded 40->64), fused log_softmax.
// BM=64, 4 warps, warp tile 16x64. Padded cols: bias -1e30 -> never max.
// ---------------------------------------------------------------------------
__global__ void __launch_bounds__(128) final_kernel(
    const __half* __restrict__ h, const float* __restrict__ W2,
    const float* __restrict__ b2, float* __restrict__ out, int M)
{
    constexpr int AP = 136;  // As pitch (rows of 128 halves)
    constexpr int BP = 72;   // Bs pitch (rows of 64 halves)
    __shared__ __half As[64 * AP];
    __shared__ __half Bs[128 * BP];

    const int t    = threadIdx.x;
    const int lane = t & 31;
    const int wid  = t >> 5;
    const int blockRow = blockIdx.x * 64;

    // Stage B: W2 [128 k x 40] -> padded fp16 [128 x 64].
    {
        const int r = t;
        __half h8[8];
        #pragma unroll
        for (int c0 = 0; c0 < 64; c0 += 8) {
            #pragma unroll
            for (int q = 0; q < 8; q++) {
                const int c = c0 + q;
                h8[q] = (c < CDIM) ? __float2half_rn(W2[r * CDIM + c])
                                   : __float2half_rn(0.0f);
            }
            *(uint4*)&Bs[r * BP + c0] = *(uint4*)h8;
        }
    }

    // Stage A: h rows [blockRow..+63] x 128 halves (padded buffer, no guard).
    {
        const int a_row = t >> 1;
        const int kg    = (t & 1) * 64;
        const uint4* src = (const uint4*)(h + (size_t)(blockRow + a_row) * HDIM + kg);
        #pragma unroll
        for (int q = 0; q < 8; q++)
            *(uint4*)&As[a_row * AP + kg + q * 8] = src[q];
    }
    __syncthreads();

    const int a_lr = lane & 15;
    const int a_lk = (lane >> 4) * 8;
    const int b_lr = (lane & 7) + ((lane >> 3) & 1) * 8;
    const int b_lcg = (lane >> 4) * 8;

    float acc[8][4];
    #pragma unroll
    for (int nt = 0; nt < 8; nt++)
        #pragma unroll
        for (int q = 0; q < 4; q++) acc[nt][q] = 0.0f;

    #pragma unroll
    for (int k0 = 0; k0 < HDIM; k0 += 16) {
        uint32_t a[4];
        ldsm_x4(a, smem_u32(&As[(wid * 16 + a_lr) * AP + k0 + a_lk]));

        uint32_t b[8][2];
        #pragma unroll
        for (int ntp = 0; ntp < 4; ntp++) {
            uint32_t r4[4];
            ldsm_x4_t(r4, smem_u32(&Bs[(k0 + b_lr) * BP + ntp * 16 + b_lcg]));
            b[ntp * 2 + 0][0] = r4[0]; b[ntp * 2 + 0][1] = r4[1];
            b[ntp * 2 + 1][0] = r4[2]; b[ntp * 2 + 1][1] = r4[3];
        }

        #pragma unroll
        for (int nt = 0; nt < 8; nt++)
            mma16816(acc[nt], a, b[nt]);
    }

    float v0[8][2], v1[8][2];
    #pragma unroll
    for (int nt = 0; nt < 8; nt++) {
        const int col = nt * 8 + (lane & 3) * 2;
        const float bx = (col     < CDIM) ? b2[col]     : -1e30f;
        const float by = (col + 1 < CDIM) ? b2[col + 1] : -1e30f;
        v0[nt][0] = acc[nt][0] + bx; v0[nt][1] = acc[nt][1] + by;
        v1[nt][0] = acc[nt][2] + bx; v1[nt][1] = acc[nt][3] + by;
    }

    float m0 = -1e30f, m1 = -1e30f;
    #pragma unroll
    for (int nt = 0; nt < 8; nt++) {
        m0 = fmaxf(m0, fmaxf(v0[nt][0], v0[nt][1]));
        m1 = fmaxf(m1, fmaxf(v1[nt][0], v1[nt][1]));
    }
    m0 = fmaxf(m0, __shfl_xor_sync(0xffffffffu, m0, 1));
    m0 = fmaxf(m0, __shfl_xor_sync(0xffffffffu, m0, 2));
    m1 = fmaxf(m1, __shfl_xor_sync(0xffffffffu, m1, 1));
    m1 = fmaxf(m1, __shfl_xor_sync(0xffffffffu, m1, 2));

    float s0 = 0.0f, s1 = 0.0f;
    #pragma unroll
    for (int nt = 0; nt < 8; nt++) {
        s0 += __expf(v0[nt][0] - m0) + __expf(v0[nt][1] - m0);
        s1 += __expf(v1[nt][0] - m1) + __expf(v1[nt][1] - m1);
    }
    s0 += __shfl_xor_sync(0xffffffffu, s0, 1);
    s0 += __shfl_xor_sync(0xffffffffu, s0, 2);
    s1 += __shfl_xor_sync(0xffffffffu, s1, 1);
    s1 += __shfl_xor_sync(0xffffffffu, s1, 2);

    const float lse0 = m0 + __logf(s0);
    const float lse1 = m1 + __logf(s1);

    const int r0 = blockRow + wid * 16 + (lane >> 2);
    const int r1 = r0 + 8;
    #pragma unroll
    for (int nt = 0; nt < 5; nt++) {        // cols 0..39 only
        const int col = nt * 8 + (lane & 3) * 2;
        if (r0 < M) {
            float2 w = make_float2(v0[nt][0] - lse0, v0[nt][1] - lse0);
            *(float2*)(out + (size_t)r0 * CDIM + col) = w;
        }
        if (r1 < M) {
            float2 w = make_float2(v1[nt][0] - lse1, v1[nt][1] - lse1);
            *(float2*)(out + (size_t)r1 * CDIM + col) = w;
        }
    }
}

// ---------------------------------------------------------------------------
// Launch sequence. Inputs: x, degree, ends, att, W0, b0, W1, b1, W2, b2
// ---------------------------------------------------------------------------
extern "C" void kernel_launch(void* const* d_in, const int* in_sizes, int n_in,
                              void* d_out, int out_size)
{
    const float* x   = (const float*)d_in[0];
    const float* deg = (const float*)d_in[1];
    const int*   ends= (const int*)  d_in[2];
    const float* att = (const float*)d_in[3];
    const float* W0  = (const float*)d_in[4];
    const float* b0  = (const float*)d_in[5];
    const float* W1  = (const float*)d_in[6];
    const float* b1  = (const float*)d_in[7];
    const float* W2  = (const float*)d_in[8];
    const float* b2  = (const float*)d_in[9];
    float* out = (float*)d_out;

    __half *bufA = nullptr, *bufB = nullptr;
    float *sdeg = nullptr, *isdeg = nullptr;
    cudaGetSymbolAddress((void**)&bufA, g_bufA);
    cudaGetSymbolAddress((void**)&bufB, g_bufB);
    cudaGetSymbolAddress((void**)&sdeg, g_sdeg);
    cudaGetSymbolAddress((void**)&isdeg, g_isdeg);

    const int gridM   = NPAD / 128;               // 782
    const int gridF   = (NNODES + 63) / 64;       // 1563
    const int gridAgg = NNODES / NPB;             // 6250

    deg_prep_kernel<<<(NNODES + 255) / 256, 256>>>(deg, sdeg, isdeg);
    // Layer 0: h = x @ W0 + b0  -> bufA (fp16, cp.async-pipelined HMMA)
    hgemm_pipe<float, 256><<<gridM, 256>>>(x, W0, b0, bufA, NNODES);
    // Agg layer 0: bufA -> bufB (relu'd)
    agg_kernel<<<gridAgg, 256>>>(bufA, bufB,
                                 ends + 0 * (size_t)KHOPS * NNODES * RWS,
                                 sdeg, isdeg, att + 0 * (KHOPS + 1));
    // Layer 1: h = bufB @ W1 + b1 -> bufA
    hgemm_pipe<__half, 128><<<gridM, 256>>>(bufB, W1, b1, bufA, NNODES);
    // Agg layer 1: bufA -> bufB (relu'd)
    agg_kernel<<<gridAgg, 256>>>(bufA, bufB,
                                 ends + 1 * (size_t)KHOPS * NNODES * RWS,
                                 sdeg, isdeg, att + 1 * (KHOPS + 1));
    // Final: logits + fused log_softmax -> out (tensor cores)
    final_kernel<<<gridF, 128>>>(bufB, W2, b2, out, NNODES);
}